// round 6
// baseline (speedup 1.0000x reference)
#include <cuda_runtime.h>

#define LN 2
#define NR 768
#define NA 14
#define TILE 32
#define NTILE (NR / TILE)          // 24
#define NFAPE (NTILE * NTILE * LN) // 1152 fape blocks
#define NLDDT 96                   // 96 lddt blocks x 8 rows
#define ROWS_PER_LDDT (NR / NLDDT) // 8

// output layout: fape_loss[2], rotamer_loss[2], final_ae[768*768], rotamer_error[-1][768], lddt[768]
#define OFF_AE   4
#define OFF_RE   (4 + NR * NR)
#define OFF_LDDT (OFF_RE + NR)

// ---- device scratch (zero-initialized at load; re-zeroed by last block every run) ----
__device__ float    g_acc[9];   // intra0,intra1,inter0,inter1,cnt_s,cnt_o,diag0,diag1,nres
__device__ unsigned g_cnt;      // fape blocks done

__device__ __forceinline__ float sqrt_approx(float x) {
    float r; asm("sqrt.approx.f32 %0, %1;" : "=f"(r) : "f"(x)); return r;
}
__device__ __forceinline__ float rsqrt_approx(float x) {
    float r; asm("rsqrt.approx.f32 %0, %1;" : "=f"(r) : "f"(x)); return r;
}
__device__ __forceinline__ float warp_sum(float v) {
#pragma unroll
    for (int o = 16; o > 0; o >>= 1) v += __shfl_down_sync(0xffffffffu, v, o);
    return v;
}

__device__ __forceinline__ void make_frame(const float n[3], const float ca[3], const float c[3],
                                           float e1[3], float e2[3], float e3[3]) {
    e1[0] = c[0] - ca[0]; e1[1] = c[1] - ca[1]; e1[2] = c[2] - ca[2];
    float s1 = e1[0]*e1[0] + e1[1]*e1[1] + e1[2]*e1[2];
    float i1 = rsqrt_approx(fmaxf(s1, 1e-6f));
    e1[0] *= i1; e1[1] *= i1; e1[2] *= i1;
    float v2[3] = { n[0]-ca[0], n[1]-ca[1], n[2]-ca[2] };
    float dt = e1[0]*v2[0] + e1[1]*v2[1] + e1[2]*v2[2];
    e2[0] = v2[0] - dt*e1[0]; e2[1] = v2[1] - dt*e1[1]; e2[2] = v2[2] - dt*e1[2];
    float s2 = e2[0]*e2[0] + e2[1]*e2[1] + e2[2]*e2[2];
    float i2 = rsqrt_approx(fmaxf(s2, 1e-6f));
    e2[0] *= i2; e2[1] *= i2; e2[2] *= i2;
    e3[0] = e1[1]*e2[2] - e1[2]*e2[1];
    e3[1] = e1[2]*e2[0] - e1[0]*e2[2];
    e3[2] = e1[0]*e2[1] - e1[1]*e2[0];
}

__device__ __forceinline__ void compute_Qo(const float* __restrict__ pred,
                                           const float* __restrict__ gt,
                                           int l, int i, float* dst /*12 floats*/) {
    const float* gb = gt + (size_t)i * NA * 3;
    float gn[3]  = { gb[0], gb[1], gb[2] };
    float gca[3] = { gb[3], gb[4], gb[5] };
    float gc[3]  = { gb[6], gb[7], gb[8] };
    float e1g[3], e2g[3], e3g[3];
    make_frame(gn, gca, gc, e1g, e2g, e3g);

    const float* pb = pred + (size_t)(l * NR + i) * NA * 3;
    float pn[3]  = { pb[0], pb[1], pb[2] };
    float pca[3] = { pb[3], pb[4], pb[5] };
    float pc[3]  = { pb[6], pb[7], pb[8] };
    float e1p[3], e2p[3], e3p[3];
    make_frame(pn, pca, pc, e1p, e2p, e3p);

#pragma unroll
    for (int d = 0; d < 3; d++) {
        float q0 = e1p[d]*e1g[0] + e2p[d]*e2g[0] + e3p[d]*e3g[0];
        float q1 = e1p[d]*e1g[1] + e2p[d]*e2g[1] + e3p[d]*e3g[1];
        float q2 = e1p[d]*e1g[2] + e2p[d]*e2g[2] + e3p[d]*e3g[2];
        dst[3*d+0] = q0; dst[3*d+1] = q1; dst[3*d+2] = q2;
        dst[9 + d] = pca[d] - (q0*gca[0] + q1*gca[1] + q2*gca[2]);
    }
}

__device__ __forceinline__ int atom_bits(const float* __restrict__ am, int i) {
    // am row: 14 floats at 56B offset -> 8B aligned; use 7x float2
    const float2* r = (const float2*)(am + (size_t)i * NA);
    int bits = 0;
#pragma unroll
    for (int k = 0; k < 7; k++) {
        float2 f = r[k];
        bits |= (f.x > 0.f) ? (1 << (2 * k)) : 0;
        bits |= (f.y > 0.f) ? (1 << (2 * k + 1)) : 0;
    }
    return bits;
}

__device__ __forceinline__ void fape_done(float* __restrict__ out) {
    __threadfence();
    unsigned done = atomicAdd(&g_cnt, 1u);
    if (done == NFAPE - 1) {
        float nres = fmaxf(g_acc[8], 1e-6f);
        float invCS = 0.1f / fmaxf(g_acc[4], 1e-6f);
        float invCO = 0.1f / fmaxf(g_acc[5], 1e-6f);
        out[0] = g_acc[0] * invCS + g_acc[2] * invCO;  // fape_loss[0]
        out[1] = g_acc[1] * invCS + g_acc[3] * invCO;  // fape_loss[1]
        out[2] = g_acc[6] / nres;                      // rotamer_loss[0]
        out[3] = g_acc[7] / nres;                      // rotamer_loss[1]
#pragma unroll
        for (int k = 0; k < 9; k++) g_acc[k] = 0.f;    // reset for next replay
        __threadfence();
        g_cnt = 0u;
    }
}

// ---- single fused kernel: 1D grid, blocks [0,NFAPE) = fape, [NFAPE, NFAPE+NLDDT) = lddt ----
// block = 256 threads (32 x 8); fape thread handles rows {ty,ty+8} then {ty+16,ty+24}.
__global__ __launch_bounds__(256, 4) void fused_kernel(const float* __restrict__ pred,
                                                       const float* __restrict__ gt,
                                                       const float* __restrict__ am,
                                                       const int* __restrict__ batch,
                                                       const int* __restrict__ chain,
                                                       float* __restrict__ out) {
    const int tid = threadIdx.x;
    const int tx = tid & 31, ty = tid >> 5;
    const int b = blockIdx.x;

    if (b >= NFAPE) {
        // ================= lDDT: 96 blocks x 8 rows =================
        __shared__ float sg[NR][3];
        __shared__ float sp[NR][3];
        __shared__ int   srm[NR];
        __shared__ float lred[8][2];
        for (int j = tid; j < NR; j += 256) {
            const float* gp = gt + ((size_t)j * NA + 1) * 3;
            sg[j][0] = gp[0]; sg[j][1] = gp[1]; sg[j][2] = gp[2];
            const float* pp = pred + ((size_t)(1 * NR + j) * NA + 1) * 3;  // pred[-1]
            sp[j][0] = pp[0]; sp[j][1] = pp[1]; sp[j][2] = pp[2];
            srm[j] = (atom_bits(am, j) != 0);
        }
        __syncthreads();

        const int i0 = (b - NFAPE) * ROWS_PER_LDDT;
#pragma unroll
        for (int r = 0; r < ROWS_PER_LDDT; r++) {
            const int i = i0 + r;
            const float gix = sg[i][0], giy = sg[i][1], giz = sg[i][2];
            const float pix = sp[i][0], piy = sp[i][1], piz = sp[i][2];
            float suml = 0.f, cnt = 0.f;
            if (srm[i]) {
                for (int j = tid; j < NR; j += 256) {
                    if (j == i || !srm[j]) continue;
                    float dx = gix - sg[j][0], dy = giy - sg[j][1], dz = giz - sg[j][2];
                    float gd = sqrt_approx(fmaxf(dx*dx + dy*dy + dz*dz, 1e-6f));
                    if (gd < 15.f) {
                        float ex = pix - sp[j][0], ey = piy - sp[j][1], ez = piz - sp[j][2];
                        float d = sqrt_approx(fmaxf(ex*ex + ey*ey + ez*ez, 1e-6f));
                        float derr = fabsf(gd - d);
                        int c = (derr < 0.5f) + (derr < 1.0f) + (derr < 2.0f) + (derr < 4.0f);
                        suml += 0.25f * (float)c;
                        cnt  += 1.f;
                    }
                }
            }
            float v0 = warp_sum(suml), v1 = warp_sum(cnt);
            if (tx == 0) { lred[ty][0] = v0; lred[ty][1] = v1; }
            __syncthreads();
            if (tid == 0) {
                float s = 0.f, c = 0.f;
#pragma unroll
                for (int w = 0; w < 8; w++) { s += lred[w][0]; c += lred[w][1]; }
                out[OFF_LDDT + i] = s / fmaxf(c, 1e-6f);
            }
            __syncthreads();
        }
        return;
    }

    // ================= FAPE tile =================
    __shared__ float4 sP[TILE * 15];
    __shared__ float4 sG[TILE * 15];
    __shared__ float  sQ[TILE * 12];
    __shared__ int    sBatI[TILE], sBatJ[TILE], sBitI[TILE], sBitJ[TILE], sChI[TILE], sChJ[TILE];
    __shared__ float  sred[8][5];
    __shared__ int    sSkip;

    const int l = b / (NTILE * NTILE);
    const int t = b % (NTILE * NTILE);
    const int i0 = (t / NTILE) * TILE, j0 = (t % NTILE) * TILE;
    float* out_ae = out + OFF_AE;

    // cheap skip decision BEFORE any staging (batch is sorted)
    if (tid == 0)
        sSkip = (batch[i0] > batch[j0 + TILE - 1]) || (batch[j0] > batch[i0 + TILE - 1]);
    __syncthreads();

    // nres contribution (24 blocks: l==0, j_tile==0) — must run even when skipped
    if (l == 0 && j0 == 0 && tid < TILE) {
        float n = warp_sum((atom_bits(am, i0 + tid) != 0) ? 1.f : 0.f);
        if (tid == 0) atomicAdd(&g_acc[8], n);
    }

    if (sSkip) {
        if (l == 1) {
#pragma unroll
            for (int r = 0; r < 4; r++)
                out_ae[(size_t)(i0 + ty + 8 * r) * NR + (j0 + tx)] = 0.f;
        }
        if (tid == 0) fape_done(out);
        return;
    }

    // staging
    if (tid < TILE) {
        compute_Qo(pred, gt, l, i0 + tid, &sQ[tid * 12]);
        sBatI[tid] = batch[i0 + tid];
        sChI[tid]  = chain[i0 + tid];
        sBitI[tid] = atom_bits(am, i0 + tid);
    } else if (tid < 2 * TILE) {
        int u = tid - TILE;
        sBatJ[u] = batch[j0 + u];
        sChJ[u]  = chain[j0 + u];
        sBitJ[u] = atom_bits(am, j0 + u);
    }
    for (int u = tid - 64; u >= 0 && u < TILE * NA; u += 192) {
        int j = u / NA, a = u % NA;
        const float* pp = pred + ((size_t)(l * NR + j0 + j) * NA + a) * 3;
        sP[j * 15 + a] = make_float4(pp[0], pp[1], pp[2], 0.f);
        const float* gp = gt + ((size_t)(j0 + j) * NA + a) * 3;
        sG[j * 15 + a] = make_float4(gp[0], gp[1], gp[2], 0.f);
    }
    __syncthreads();

    const int batJ = sBatJ[tx], bitJ = sBitJ[tx], chJ = sChJ[tx];
    float pIntra = 0.f, pInter = 0.f, pCntS = 0.f, pCntO = 0.f, pDiag = 0.f;

#pragma unroll
    for (int pass = 0; pass < 2; pass++) {
        // two rows per pass: ty + 16*pass, ty + 16*pass + 8
        float q[2][12];
        unsigned mb[2];
#pragma unroll
        for (int r = 0; r < 2; r++) {
            const int row = ty + 16 * pass + 8 * r;
#pragma unroll
            for (int k = 0; k < 12; k++) q[r][k] = sQ[row * 12 + k];
            mb[r] = (sBatI[row] == batJ) ? (unsigned)(sBitI[row] & bitJ) : 0u;
        }

        float se[2] = {0.f, 0.f};
#pragma unroll
        for (int a = 0; a < NA; a++) {
            const float4 g = sG[tx * 15 + a];
            const float4 p = sP[tx * 15 + a];
#pragma unroll
            for (int r = 0; r < 2; r++) {
                float w0 = fmaf(q[r][0], g.x, fmaf(q[r][1], g.y, fmaf(q[r][2], g.z, q[r][9])));
                float w1 = fmaf(q[r][3], g.x, fmaf(q[r][4], g.y, fmaf(q[r][5], g.z, q[r][10])));
                float w2 = fmaf(q[r][6], g.x, fmaf(q[r][7], g.y, fmaf(q[r][8], g.z, q[r][11])));
                float d0 = p.x - w0, d1 = p.y - w1, d2 = p.z - w2;
                float n2 = fmaf(d0, d0, fmaf(d1, d1, d2 * d2));
                float err = sqrt_approx(fmaxf(n2, 1e-6f));
                se[r] += ((mb[r] >> a) & 1u) ? err : 0.f;
            }
        }

#pragma unroll
        for (int r = 0; r < 2; r++) {
            const int row = ty + 16 * pass + 8 * r;
            const int i = i0 + row, j = j0 + tx;
            float fape = __fdividef(se[r], fmaxf((float)__popc(mb[r]), 1e-6f));
            if (l == 1) out_ae[(size_t)i * NR + j] = fape;
            if (mb[r] != 0u) {
                float clip = fminf(fape, 10.f);
                if (sChI[row] == chJ) { pIntra += clip; pCntS += 1.f; }
                else                  { pInter += clip; pCntO += 1.f; }
            }
            if (i == j) {
                pDiag += fape;
                if (l == 1) out[OFF_RE + i] = fape;
            }
        }
    }

    float vals[5] = { pIntra, pInter, pCntS, pCntO, pDiag };
#pragma unroll
    for (int k = 0; k < 5; k++) {
        float v = warp_sum(vals[k]);
        if (tx == 0) sred[ty][k] = v;
    }
    __syncthreads();
    if (tid < 5) {
        float v = 0.f;
#pragma unroll
        for (int w = 0; w < 8; w++) v += sred[w][tid];
        if (tid == 0) atomicAdd(&g_acc[0 + l], v);
        else if (tid == 1) atomicAdd(&g_acc[2 + l], v);
        else if (tid == 2) { if (l == 0) atomicAdd(&g_acc[4], v); }
        else if (tid == 3) { if (l == 0) atomicAdd(&g_acc[5], v); }
        else atomicAdd(&g_acc[6 + l], v);
    }

    __syncthreads();
    if (tid == 0) fape_done(out);
}

extern "C" void kernel_launch(void* const* d_in, const int* in_sizes, int n_in,
                              void* d_out, int out_size) {
    const float* pred  = (const float*)d_in[0];
    const float* gt    = (const float*)d_in[1];
    const float* am    = (const float*)d_in[2];
    const int*   batch = (const int*)d_in[3];
    const int*   chain = (const int*)d_in[4];
    float* out = (float*)d_out;

    fused_kernel<<<NFAPE + NLDDT, 256>>>(pred, gt, am, batch, chain, out);
}

// round 7
// speedup vs baseline: 1.1597x; 1.1597x over previous
#include <cuda_runtime.h>

#define LN 2
#define NR 768
#define NA 14
#define TILE 32
#define NTILE (NR / TILE)          // 24
#define NFAPE (NTILE * NTILE * LN) // 1152 fape blocks
#define NLDDT 96                   // 96 lddt blocks x 8 rows
#define ROWS_PER_LDDT (NR / NLDDT) // 8

// output layout: fape_loss[2], rotamer_loss[2], final_ae[768*768], rotamer_error[-1][768], lddt[768]
#define OFF_AE   4
#define OFF_RE   (4 + NR * NR)
#define OFF_LDDT (OFF_RE + NR)

typedef unsigned long long u64;

// ---- device scratch (zero-initialized at load; re-zeroed by last block every run) ----
__device__ float    g_acc[9];   // intra0,intra1,inter0,inter1,cnt_s,cnt_o,diag0,diag1,nres
__device__ unsigned g_cnt;      // fape blocks done

#define FMA2(d, a, b, c) asm("fma.rn.f32x2 %0, %1, %2, %3;" : "=l"(d) : "l"(a), "l"(b), "l"(c))
#define ADD2(d, a, b)    asm("add.rn.f32x2 %0, %1, %2;" : "=l"(d) : "l"(a), "l"(b))
#define MUL2(d, a, b)    asm("mul.rn.f32x2 %0, %1, %2;" : "=l"(d) : "l"(a), "l"(b))
#define PACK2(d, lo, hi) asm("mov.b64 %0, {%1, %2};" : "=l"(d) : "f"(lo), "f"(hi))
#define UNPK2(lo, hi, s) asm("mov.b64 {%0, %1}, %2;" : "=f"(lo), "=f"(hi) : "l"(s))

__device__ __forceinline__ u64 bcast2(float f) { u64 v; PACK2(v, f, f); return v; }

__device__ __forceinline__ float sqrt_approx(float x) {
    float r; asm("sqrt.approx.f32 %0, %1;" : "=f"(r) : "f"(x)); return r;
}
__device__ __forceinline__ float rsqrt_approx(float x) {
    float r; asm("rsqrt.approx.f32 %0, %1;" : "=f"(r) : "f"(x)); return r;
}
__device__ __forceinline__ float warp_sum(float v) {
#pragma unroll
    for (int o = 16; o > 0; o >>= 1) v += __shfl_down_sync(0xffffffffu, v, o);
    return v;
}

__device__ __forceinline__ void make_frame(const float n[3], const float ca[3], const float c[3],
                                           float e1[3], float e2[3], float e3[3]) {
    e1[0] = c[0] - ca[0]; e1[1] = c[1] - ca[1]; e1[2] = c[2] - ca[2];
    float s1 = e1[0]*e1[0] + e1[1]*e1[1] + e1[2]*e1[2];
    float i1 = rsqrt_approx(fmaxf(s1, 1e-6f));
    e1[0] *= i1; e1[1] *= i1; e1[2] *= i1;
    float v2[3] = { n[0]-ca[0], n[1]-ca[1], n[2]-ca[2] };
    float dt = e1[0]*v2[0] + e1[1]*v2[1] + e1[2]*v2[2];
    e2[0] = v2[0] - dt*e1[0]; e2[1] = v2[1] - dt*e1[1]; e2[2] = v2[2] - dt*e1[2];
    float s2 = e2[0]*e2[0] + e2[1]*e2[1] + e2[2]*e2[2];
    float i2 = rsqrt_approx(fmaxf(s2, 1e-6f));
    e2[0] *= i2; e2[1] *= i2; e2[2] *= i2;
    e3[0] = e1[1]*e2[2] - e1[2]*e2[1];
    e3[1] = e1[2]*e2[0] - e1[0]*e2[2];
    e3[2] = e1[0]*e2[1] - e1[1]*e2[0];
}

__device__ __forceinline__ void compute_Qo(const float* __restrict__ pred,
                                           const float* __restrict__ gt,
                                           int l, int i, float* dst /*12 floats*/) {
    const float* gb = gt + (size_t)i * NA * 3;
    float gn[3]  = { gb[0], gb[1], gb[2] };
    float gca[3] = { gb[3], gb[4], gb[5] };
    float gc[3]  = { gb[6], gb[7], gb[8] };
    float e1g[3], e2g[3], e3g[3];
    make_frame(gn, gca, gc, e1g, e2g, e3g);

    const float* pb = pred + (size_t)(l * NR + i) * NA * 3;
    float pn[3]  = { pb[0], pb[1], pb[2] };
    float pca[3] = { pb[3], pb[4], pb[5] };
    float pc[3]  = { pb[6], pb[7], pb[8] };
    float e1p[3], e2p[3], e3p[3];
    make_frame(pn, pca, pc, e1p, e2p, e3p);

#pragma unroll
    for (int d = 0; d < 3; d++) {
        float q0 = e1p[d]*e1g[0] + e2p[d]*e2g[0] + e3p[d]*e3g[0];
        float q1 = e1p[d]*e1g[1] + e2p[d]*e2g[1] + e3p[d]*e3g[1];
        float q2 = e1p[d]*e1g[2] + e2p[d]*e2g[2] + e3p[d]*e3g[2];
        dst[3*d+0] = q0; dst[3*d+1] = q1; dst[3*d+2] = q2;
        dst[9 + d] = pca[d] - (q0*gca[0] + q1*gca[1] + q2*gca[2]);
    }
}

__device__ __forceinline__ int atom_bits(const float* __restrict__ am, int i) {
    int bits = 0;
#pragma unroll
    for (int a = 0; a < NA; a++)
        if (am[i * NA + a] > 0.f) bits |= (1 << a);
    return bits;
}

// ---- single fused kernel: 1D grid, blocks [0,NFAPE) = fape, [NFAPE,...) = lddt ----
// block = 256 threads (32 x 8); fape thread handles 4 i-rows (ty + 8r) for one j.
__global__ __launch_bounds__(256) void fused_kernel(const float* __restrict__ pred,
                                                    const float* __restrict__ gt,
                                                    const float* __restrict__ am,
                                                    const int* __restrict__ batch,
                                                    const int* __restrict__ chain,
                                                    float* __restrict__ out) {
    const int tid = threadIdx.x;
    const int tx = tid & 31, ty = tid >> 5;
    const int b = blockIdx.x;

    if (b >= NFAPE) {
        // ================= lDDT: 96 blocks x 8 rows =================
        __shared__ float sg[NR][3];
        __shared__ float sp[NR][3];
        __shared__ int   srm[NR];
        __shared__ float lred[8][2];
        for (int j = tid; j < NR; j += 256) {
            const float* gp = gt + ((size_t)j * NA + 1) * 3;
            sg[j][0] = gp[0]; sg[j][1] = gp[1]; sg[j][2] = gp[2];
            const float* pp = pred + ((size_t)(1 * NR + j) * NA + 1) * 3;  // pred[-1]
            sp[j][0] = pp[0]; sp[j][1] = pp[1]; sp[j][2] = pp[2];
            srm[j] = (atom_bits(am, j) != 0);
        }
        __syncthreads();

        const int i0 = (b - NFAPE) * ROWS_PER_LDDT;
#pragma unroll
        for (int r = 0; r < ROWS_PER_LDDT; r++) {
            const int i = i0 + r;
            const float gix = sg[i][0], giy = sg[i][1], giz = sg[i][2];
            const float pix = sp[i][0], piy = sp[i][1], piz = sp[i][2];
            float suml = 0.f, cnt = 0.f;
            if (srm[i]) {
                for (int j = tid; j < NR; j += 256) {
                    if (j == i || !srm[j]) continue;
                    float dx = gix - sg[j][0], dy = giy - sg[j][1], dz = giz - sg[j][2];
                    float gd = sqrt_approx(fmaxf(dx*dx + dy*dy + dz*dz, 1e-6f));
                    if (gd < 15.f) {
                        float ex = pix - sp[j][0], ey = piy - sp[j][1], ez = piz - sp[j][2];
                        float d = sqrt_approx(fmaxf(ex*ex + ey*ey + ez*ez, 1e-6f));
                        float derr = fabsf(gd - d);
                        int c = (derr < 0.5f) + (derr < 1.0f) + (derr < 2.0f) + (derr < 4.0f);
                        suml += 0.25f * (float)c;
                        cnt  += 1.f;
                    }
                }
            }
            float v0 = warp_sum(suml), v1 = warp_sum(cnt);
            if (tx == 0) { lred[ty][0] = v0; lred[ty][1] = v1; }
            __syncthreads();
            if (tid == 0) {
                float s = 0.f, c = 0.f;
#pragma unroll
                for (int w = 0; w < 8; w++) { s += lred[w][0]; c += lred[w][1]; }
                out[OFF_LDDT + i] = s / fmaxf(c, 1e-6f);
            }
            __syncthreads();
        }
        return;
    }

    // ================= FAPE tile =================
    // sD[j]: 14 atoms x 3 ulonglong2 = [(gx2,gy2),(gz2,px2),(py2,pz2)], padded to 45 (720B/j: conflict-free)
    __shared__ ulonglong2 sD[TILE][45];
    __shared__ float  sQ[TILE * 12];
    __shared__ int    sBatI[TILE], sBatJ[TILE], sBitI[TILE], sBitJ[TILE], sChI[TILE], sChJ[TILE];
    __shared__ float  sred[8][5];

    const int l = b / (NTILE * NTILE);
    const int t = b % (NTILE * NTILE);
    const int i0 = (t / NTILE) * TILE, j0 = (t % NTILE) * TILE;
    float* out_ae = out + OFF_AE;

    if (tid < TILE) {
        compute_Qo(pred, gt, l, i0 + tid, &sQ[tid * 12]);
        sBatI[tid] = batch[i0 + tid];
        sChI[tid]  = chain[i0 + tid];
        sBitI[tid] = atom_bits(am, i0 + tid);
    } else if (tid < 2 * TILE) {
        int u = tid - TILE;
        sBatJ[u] = batch[j0 + u];
        sChJ[u]  = chain[j0 + u];
        sBitJ[u] = atom_bits(am, j0 + u);
    }
    // all threads: stage pre-broadcast point pairs (448 entries, 2 rounds)
    for (int u = tid; u < TILE * NA; u += 256) {
        int j = u / NA, a = u % NA;
        const float* gp = gt + ((size_t)(j0 + j) * NA + a) * 3;
        const float* pp = pred + ((size_t)(l * NR + j0 + j) * NA + a) * 3;
        ulonglong2 v0, v1, v2;
        v0.x = bcast2(gp[0]); v0.y = bcast2(gp[1]);
        v1.x = bcast2(gp[2]); v1.y = bcast2(pp[0]);
        v2.x = bcast2(pp[1]); v2.y = bcast2(pp[2]);
        sD[j][a * 3 + 0] = v0;
        sD[j][a * 3 + 1] = v1;
        sD[j][a * 3 + 2] = v2;
    }
    __syncthreads();

    // nres contribution (24 blocks: l==0, j_tile==0)
    if (l == 0 && j0 == 0 && tid < TILE) {
        float n = warp_sum((sBitI[tid] != 0) ? 1.f : 0.f);
        if (tid == 0) atomicAdd(&g_acc[8], n);
    }

    const bool skip = (sBatI[0] > sBatJ[TILE - 1]) || (sBatJ[0] > sBatI[TILE - 1]);

    if (!skip) {
        // rows r=0..3 -> ty + 8r; pairs (r0,r1), (r2,r3)
        const int batJ = sBatJ[tx], bitJ = sBitJ[tx];
        unsigned mb[4];
#pragma unroll
        for (int r = 0; r < 4; r++) {
            const int row = ty + 8 * r;
            mb[r] = (sBatI[row] == batJ) ? (unsigned)(sBitI[row] & bitJ) : 0u;
        }
        // negated Q (9) and o (3), packed per pair — once, outside the loop
        u64 nq[2][9], no[2][3];
#pragma unroll
        for (int P = 0; P < 2; P++) {
            const int rA = ty + 8 * (2 * P), rB = ty + 8 * (2 * P + 1);
#pragma unroll
            for (int k = 0; k < 9; k++) PACK2(nq[P][k], -sQ[rA * 12 + k], -sQ[rB * 12 + k]);
#pragma unroll
            for (int k = 0; k < 3; k++) PACK2(no[P][k], -sQ[rA * 12 + 9 + k], -sQ[rB * 12 + 9 + k]);
        }

        float se[4] = {0.f, 0.f, 0.f, 0.f};
#pragma unroll
        for (int a = 0; a < NA; a++) {
            const ulonglong2 t0 = sD[tx][a * 3 + 0];  // gx2, gy2
            const ulonglong2 t1 = sD[tx][a * 3 + 1];  // gz2, px2
            const ulonglong2 t2 = sD[tx][a * 3 + 2];  // py2, pz2
#pragma unroll
            for (int P = 0; P < 2; P++) {
                u64 w0, w1, w2, n2;
                FMA2(w0, nq[P][2], t1.x, no[P][0]); FMA2(w0, nq[P][1], t0.y, w0); FMA2(w0, nq[P][0], t0.x, w0);
                FMA2(w1, nq[P][5], t1.x, no[P][1]); FMA2(w1, nq[P][4], t0.y, w1); FMA2(w1, nq[P][3], t0.x, w1);
                FMA2(w2, nq[P][8], t1.x, no[P][2]); FMA2(w2, nq[P][7], t0.y, w2); FMA2(w2, nq[P][6], t0.x, w2);
                ADD2(w0, t1.y, w0); ADD2(w1, t2.x, w1); ADD2(w2, t2.y, w2);
                MUL2(n2, w0, w0); FMA2(n2, w1, w1, n2); FMA2(n2, w2, w2, n2);
                float nA, nB;
                UNPK2(nA, nB, n2);
                float eA = sqrt_approx(fmaxf(nA, 1e-6f));
                float eB = sqrt_approx(fmaxf(nB, 1e-6f));
                se[2*P]   += ((mb[2*P]   >> a) & 1u) ? eA : 0.f;
                se[2*P+1] += ((mb[2*P+1] >> a) & 1u) ? eB : 0.f;
            }
        }

        float pIntra = 0.f, pInter = 0.f, pCntS = 0.f, pCntO = 0.f, pDiag = 0.f;
        const int chJ = sChJ[tx];
#pragma unroll
        for (int r = 0; r < 4; r++) {
            const int row = ty + 8 * r;
            const int i = i0 + row, j = j0 + tx;
            float fape = __fdividef(se[r], fmaxf((float)__popc(mb[r]), 1e-6f));
            if (l == 1) out_ae[(size_t)i * NR + j] = fape;
            if (mb[r] != 0u) {
                float clip = fminf(fape, 10.f);
                if (sChI[row] == chJ) { pIntra += clip; pCntS += 1.f; }
                else                  { pInter += clip; pCntO += 1.f; }
            }
            if (i == j) {
                pDiag += fape;
                if (l == 1) out[OFF_RE + i] = fape;
            }
        }

        float vals[5] = { pIntra, pInter, pCntS, pCntO, pDiag };
#pragma unroll
        for (int k = 0; k < 5; k++) {
            float v = warp_sum(vals[k]);
            if (tx == 0) sred[ty][k] = v;
        }
        __syncthreads();
        if (tid < 5) {
            float v = 0.f;
#pragma unroll
            for (int w = 0; w < 8; w++) v += sred[w][tid];
            if (tid == 0) atomicAdd(&g_acc[0 + l], v);
            else if (tid == 1) atomicAdd(&g_acc[2 + l], v);
            else if (tid == 2) { if (l == 0) atomicAdd(&g_acc[4], v); }
            else if (tid == 3) { if (l == 0) atomicAdd(&g_acc[5], v); }
            else atomicAdd(&g_acc[6 + l], v);
        }
    } else if (l == 1) {
#pragma unroll
        for (int r = 0; r < 4; r++)
            out_ae[(size_t)(i0 + ty + 8 * r) * NR + (j0 + tx)] = 0.f;
    }

    // done-counter; last fape block finalizes scalars and resets state
    __syncthreads();
    if (tid == 0) {
        __threadfence();
        unsigned done = atomicAdd(&g_cnt, 1u);
        if (done == NFAPE - 1) {
            float nres = fmaxf(g_acc[8], 1e-6f);
            float invCS = 0.1f / fmaxf(g_acc[4], 1e-6f);
            float invCO = 0.1f / fmaxf(g_acc[5], 1e-6f);
            out[0] = g_acc[0] * invCS + g_acc[2] * invCO;  // fape_loss[0]
            out[1] = g_acc[1] * invCS + g_acc[3] * invCO;  // fape_loss[1]
            out[2] = g_acc[6] / nres;                      // rotamer_loss[0]
            out[3] = g_acc[7] / nres;                      // rotamer_loss[1]
#pragma unroll
            for (int k = 0; k < 9; k++) g_acc[k] = 0.f;    // reset for next replay
            __threadfence();
            g_cnt = 0u;
        }
    }
}

extern "C" void kernel_launch(void* const* d_in, const int* in_sizes, int n_in,
                              void* d_out, int out_size) {
    const float* pred  = (const float*)d_in[0];
    const float* gt    = (const float*)d_in[1];
    const float* am    = (const float*)d_in[2];
    const int*   batch = (const int*)d_in[3];
    const int*   chain = (const int*)d_in[4];
    float* out = (float*)d_out;

    fused_kernel<<<NFAPE + NLDDT, 256>>>(pred, gt, am, batch, chain, out);
}

// round 8
// speedup vs baseline: 1.2514x; 1.0790x over previous
#include <cuda_runtime.h>

#define LN 2
#define NR 768
#define NA 14
#define TILE 32
#define NTILE (NR / TILE)          // 24
#define NFAPE (NTILE * NTILE * LN) // 1152 fape blocks
#define NLDDT 96                   // 96 lddt blocks x 8 rows
#define ROWS_PER_LDDT (NR / NLDDT) // 8

// output layout: fape_loss[2], rotamer_loss[2], final_ae[768*768], rotamer_error[-1][768], lddt[768]
#define OFF_AE   4
#define OFF_RE   (4 + NR * NR)
#define OFF_LDDT (OFF_RE + NR)

// ---- device scratch (zero-initialized at load; re-zeroed by last block every run) ----
__device__ float    g_acc[9];   // intra0,intra1,inter0,inter1,cnt_s,cnt_o,diag0,diag1,nres
__device__ unsigned g_cnt;      // fape blocks done

__device__ __forceinline__ float sqrt_approx(float x) {
    float r; asm("sqrt.approx.f32 %0, %1;" : "=f"(r) : "f"(x)); return r;
}
__device__ __forceinline__ float rsqrt_approx(float x) {
    float r; asm("rsqrt.approx.f32 %0, %1;" : "=f"(r) : "f"(x)); return r;
}
__device__ __forceinline__ float warp_sum(float v) {
#pragma unroll
    for (int o = 16; o > 0; o >>= 1) v += __shfl_down_sync(0xffffffffu, v, o);
    return v;
}

__device__ __forceinline__ void make_frame(const float n[3], const float ca[3], const float c[3],
                                           float e1[3], float e2[3], float e3[3]) {
    e1[0] = c[0] - ca[0]; e1[1] = c[1] - ca[1]; e1[2] = c[2] - ca[2];
    float s1 = e1[0]*e1[0] + e1[1]*e1[1] + e1[2]*e1[2];
    float i1 = rsqrt_approx(fmaxf(s1, 1e-6f));
    e1[0] *= i1; e1[1] *= i1; e1[2] *= i1;
    float v2[3] = { n[0]-ca[0], n[1]-ca[1], n[2]-ca[2] };
    float dt = e1[0]*v2[0] + e1[1]*v2[1] + e1[2]*v2[2];
    e2[0] = v2[0] - dt*e1[0]; e2[1] = v2[1] - dt*e1[1]; e2[2] = v2[2] - dt*e1[2];
    float s2 = e2[0]*e2[0] + e2[1]*e2[1] + e2[2]*e2[2];
    float i2 = rsqrt_approx(fmaxf(s2, 1e-6f));
    e2[0] *= i2; e2[1] *= i2; e2[2] *= i2;
    e3[0] = e1[1]*e2[2] - e1[2]*e2[1];
    e3[1] = e1[2]*e2[0] - e1[0]*e2[2];
    e3[2] = e1[0]*e2[1] - e1[1]*e2[0];
}

__device__ __forceinline__ void compute_Qo(const float* __restrict__ pred,
                                           const float* __restrict__ gt,
                                           int l, int i, float* dst /*12 floats*/) {
    const float* gb = gt + (size_t)i * NA * 3;
    float gn[3]  = { gb[0], gb[1], gb[2] };
    float gca[3] = { gb[3], gb[4], gb[5] };
    float gc[3]  = { gb[6], gb[7], gb[8] };
    float e1g[3], e2g[3], e3g[3];
    make_frame(gn, gca, gc, e1g, e2g, e3g);

    const float* pb = pred + (size_t)(l * NR + i) * NA * 3;
    float pn[3]  = { pb[0], pb[1], pb[2] };
    float pca[3] = { pb[3], pb[4], pb[5] };
    float pc[3]  = { pb[6], pb[7], pb[8] };
    float e1p[3], e2p[3], e3p[3];
    make_frame(pn, pca, pc, e1p, e2p, e3p);

#pragma unroll
    for (int d = 0; d < 3; d++) {
        float q0 = e1p[d]*e1g[0] + e2p[d]*e2g[0] + e3p[d]*e3g[0];
        float q1 = e1p[d]*e1g[1] + e2p[d]*e2g[1] + e3p[d]*e3g[1];
        float q2 = e1p[d]*e1g[2] + e2p[d]*e2g[2] + e3p[d]*e3g[2];
        dst[3*d+0] = q0; dst[3*d+1] = q1; dst[3*d+2] = q2;
        dst[9 + d] = pca[d] - (q0*gca[0] + q1*gca[1] + q2*gca[2]);
    }
}

__device__ __forceinline__ int atom_bits(const float* __restrict__ am, int i) {
    int bits = 0;
#pragma unroll
    for (int a = 0; a < NA; a++)
        if (am[i * NA + a] > 0.f) bits |= (1 << a);
    return bits;
}

// ---- single fused kernel: 1D grid, blocks [0,NFAPE) = fape, [NFAPE,...) = lddt ----
// block = 256 threads (32 x 8); fape thread handles 4 i-rows (ty + 8r) for one j.
__global__ __launch_bounds__(256) void fused_kernel(const float* __restrict__ pred,
                                                    const float* __restrict__ gt,
                                                    const float* __restrict__ am,
                                                    const int* __restrict__ batch,
                                                    const int* __restrict__ chain,
                                                    float* __restrict__ out) {
    const int tid = threadIdx.x;
    const int tx = tid & 31, ty = tid >> 5;
    const int b = blockIdx.x;

    if (b >= NFAPE) {
        // ================= lDDT: 96 blocks x 8 rows =================
        __shared__ float sg[NR][3];
        __shared__ float sp[NR][3];
        __shared__ int   srm[NR];
        __shared__ float lred[8][2];
        for (int j = tid; j < NR; j += 256) {
            const float* gp = gt + ((size_t)j * NA + 1) * 3;
            sg[j][0] = gp[0]; sg[j][1] = gp[1]; sg[j][2] = gp[2];
            const float* pp = pred + ((size_t)(1 * NR + j) * NA + 1) * 3;  // pred[-1]
            sp[j][0] = pp[0]; sp[j][1] = pp[1]; sp[j][2] = pp[2];
            srm[j] = (atom_bits(am, j) != 0);
        }
        __syncthreads();

        const int i0 = (b - NFAPE) * ROWS_PER_LDDT;
#pragma unroll
        for (int r = 0; r < ROWS_PER_LDDT; r++) {
            const int i = i0 + r;
            const float gix = sg[i][0], giy = sg[i][1], giz = sg[i][2];
            const float pix = sp[i][0], piy = sp[i][1], piz = sp[i][2];
            float suml = 0.f, cnt = 0.f;
            if (srm[i]) {
                for (int j = tid; j < NR; j += 256) {
                    if (j == i || !srm[j]) continue;
                    float dx = gix - sg[j][0], dy = giy - sg[j][1], dz = giz - sg[j][2];
                    float gd = sqrt_approx(fmaxf(dx*dx + dy*dy + dz*dz, 1e-6f));
                    if (gd < 15.f) {
                        float ex = pix - sp[j][0], ey = piy - sp[j][1], ez = piz - sp[j][2];
                        float d = sqrt_approx(fmaxf(ex*ex + ey*ey + ez*ez, 1e-6f));
                        float derr = fabsf(gd - d);
                        int c = (derr < 0.5f) + (derr < 1.0f) + (derr < 2.0f) + (derr < 4.0f);
                        suml += 0.25f * (float)c;
                        cnt  += 1.f;
                    }
                }
            }
            float v0 = warp_sum(suml), v1 = warp_sum(cnt);
            if (tx == 0) { lred[ty][0] = v0; lred[ty][1] = v1; }
            __syncthreads();
            if (tid == 0) {
                float s = 0.f, c = 0.f;
#pragma unroll
                for (int w = 0; w < 8; w++) { s += lred[w][0]; c += lred[w][1]; }
                out[OFF_LDDT + i] = s / fmaxf(c, 1e-6f);
            }
            __syncthreads();
        }
        return;
    }

    // ================= FAPE tile =================
    __shared__ float4 sP[TILE * 15];
    __shared__ float4 sG[TILE * 15];
    __shared__ float  sQ[TILE * 12];
    __shared__ int    sBatI[TILE], sBatJ[TILE], sBitI[TILE], sBitJ[TILE], sChI[TILE], sChJ[TILE];
    __shared__ float  sred[8][5];

    const int l = b / (NTILE * NTILE);
    const int t = b % (NTILE * NTILE);
    const int i0 = (t / NTILE) * TILE, j0 = (t % NTILE) * TILE;
    float* out_ae = out + OFF_AE;

    if (tid < TILE) {
        compute_Qo(pred, gt, l, i0 + tid, &sQ[tid * 12]);
        sBatI[tid] = batch[i0 + tid];
        sChI[tid]  = chain[i0 + tid];
        sBitI[tid] = atom_bits(am, i0 + tid);
    } else if (tid < 2 * TILE) {
        int u = tid - TILE;
        sBatJ[u] = batch[j0 + u];
        sChJ[u]  = chain[j0 + u];
        sBitJ[u] = atom_bits(am, j0 + u);
    }
    for (int u = tid - 64; u >= 0 && u < TILE * NA; u += 192) {
        int j = u / NA, a = u % NA;
        const float* pp = pred + ((size_t)(l * NR + j0 + j) * NA + a) * 3;
        sP[j * 15 + a] = make_float4(pp[0], pp[1], pp[2], 0.f);
        const float* gp = gt + ((size_t)(j0 + j) * NA + a) * 3;
        sG[j * 15 + a] = make_float4(gp[0], gp[1], gp[2], 0.f);
    }
    __syncthreads();

    // nres contribution (24 blocks: l==0, j_tile==0)
    if (l == 0 && j0 == 0 && tid < TILE) {
        float n = warp_sum((sBitI[tid] != 0) ? 1.f : 0.f);
        if (tid == 0) atomicAdd(&g_acc[8], n);
    }

    const bool skip = (sBatI[0] > sBatJ[TILE - 1]) || (sBatJ[0] > sBatI[TILE - 1]);

    if (!skip) {
        const int batJ = sBatJ[tx], bitJ = sBitJ[tx];
        float q[4][12];
        unsigned mb[4];
#pragma unroll
        for (int r = 0; r < 4; r++) {
            const int row = ty + 8 * r;
#pragma unroll
            for (int k = 0; k < 12; k++) q[r][k] = sQ[row * 12 + k];
            mb[r] = (sBatI[row] == batJ) ? (unsigned)(sBitI[row] & bitJ) : 0u;
        }

        float se[4] = {0.f, 0.f, 0.f, 0.f};
#pragma unroll
        for (int a = 0; a < NA; a++) {
            const float4 g = sG[tx * 15 + a];
            const float4 p = sP[tx * 15 + a];
#pragma unroll
            for (int r = 0; r < 4; r++) {
                float w0 = fmaf(q[r][0], g.x, fmaf(q[r][1], g.y, fmaf(q[r][2], g.z, q[r][9])));
                float w1 = fmaf(q[r][3], g.x, fmaf(q[r][4], g.y, fmaf(q[r][5], g.z, q[r][10])));
                float w2 = fmaf(q[r][6], g.x, fmaf(q[r][7], g.y, fmaf(q[r][8], g.z, q[r][11])));
                float d0 = p.x - w0, d1 = p.y - w1, d2 = p.z - w2;
                float n2 = fmaf(d0, d0, fmaf(d1, d1, d2 * d2));
                float err = sqrt_approx(fmaxf(n2, 1e-6f));
                se[r] += ((mb[r] >> a) & 1u) ? err : 0.f;
            }
        }

        float pIntra = 0.f, pInter = 0.f, pCntS = 0.f, pCntO = 0.f, pDiag = 0.f;
        const int chJ = sChJ[tx];
#pragma unroll
        for (int r = 0; r < 4; r++) {
            const int row = ty + 8 * r;
            const int i = i0 + row, j = j0 + tx;
            float fape = __fdividef(se[r], fmaxf((float)__popc(mb[r]), 1e-6f));
            if (l == 1) out_ae[(size_t)i * NR + j] = fape;
            if (mb[r] != 0u) {
                float clip = fminf(fape, 10.f);
                if (sChI[row] == chJ) { pIntra += clip; pCntS += 1.f; }
                else                  { pInter += clip; pCntO += 1.f; }
            }
            if (i == j) {
                pDiag += fape;
                if (l == 1) out[OFF_RE + i] = fape;
            }
        }

        float vals[5] = { pIntra, pInter, pCntS, pCntO, pDiag };
#pragma unroll
        for (int k = 0; k < 5; k++) {
            float v = warp_sum(vals[k]);
            if (tx == 0) sred[ty][k] = v;
        }
        __syncthreads();
        if (tid < 5) {
            float v = 0.f;
#pragma unroll
            for (int w = 0; w < 8; w++) v += sred[w][tid];
            if (tid == 0) atomicAdd(&g_acc[0 + l], v);
            else if (tid == 1) atomicAdd(&g_acc[2 + l], v);
            else if (tid == 2) { if (l == 0) atomicAdd(&g_acc[4], v); }
            else if (tid == 3) { if (l == 0) atomicAdd(&g_acc[5], v); }
            else atomicAdd(&g_acc[6 + l], v);
        }
    } else if (l == 1) {
#pragma unroll
        for (int r = 0; r < 4; r++)
            out_ae[(size_t)(i0 + ty + 8 * r) * NR + (j0 + tx)] = 0.f;
    }

    // done-counter; last fape block finalizes scalars and resets state
    __syncthreads();
    if (tid == 0) {
        __threadfence();
        unsigned done = atomicAdd(&g_cnt, 1u);
        if (done == NFAPE - 1) {
            float nres = fmaxf(g_acc[8], 1e-6f);
            float invCS = 0.1f / fmaxf(g_acc[4], 1e-6f);
            float invCO = 0.1f / fmaxf(g_acc[5], 1e-6f);
            out[0] = g_acc[0] * invCS + g_acc[2] * invCO;  // fape_loss[0]
            out[1] = g_acc[1] * invCS + g_acc[3] * invCO;  // fape_loss[1]
            out[2] = g_acc[6] / nres;                      // rotamer_loss[0]
            out[3] = g_acc[7] / nres;                      // rotamer_loss[1]
#pragma unroll
            for (int k = 0; k < 9; k++) g_acc[k] = 0.f;    // reset for next replay
            __threadfence();
            g_cnt = 0u;
        }
    }
}

extern "C" void kernel_launch(void* const* d_in, const int* in_sizes, int n_in,
                              void* d_out, int out_size) {
    const float* pred  = (const float*)d_in[0];
    const float* gt    = (const float*)d_in[1];
    const float* am    = (const float*)d_in[2];
    const int*   batch = (const int*)d_in[3];
    const int*   chain = (const int*)d_in[4];
    float* out = (float*)d_out;

    fused_kernel<<<NFAPE + NLDDT, 256>>>(pred, gt, am, batch, chain, out);
}

// round 9
// speedup vs baseline: 1.3318x; 1.0643x over previous
#include <cuda_runtime.h>

#define LN 2
#define NR 768
#define NA 14
#define TILE 32
#define NTILE (NR / TILE)          // 24
#define NFAPE (NTILE * NTILE * LN) // 1152 fape blocks
#define NLDDT 96                   // 96 lddt blocks x 8 rows
#define ROWS_PER_LDDT (NR / NLDDT) // 8

// output layout: fape_loss[2], rotamer_loss[2], final_ae[768*768], rotamer_error[-1][768], lddt[768]
#define OFF_AE   4
#define OFF_RE   (4 + NR * NR)
#define OFF_LDDT (OFF_RE + NR)

// ---- device scratch (zero-initialized at load; re-zeroed by last block every run) ----
__device__ float    g_acc[9];   // intra0,intra1,inter0,inter1,cnt_s,cnt_o,diag0,diag1,nres
__device__ unsigned g_cnt;      // fape blocks done

__device__ __forceinline__ float sqrt_approx(float x) {
    float r; asm("sqrt.approx.f32 %0, %1;" : "=f"(r) : "f"(x)); return r;
}
__device__ __forceinline__ float rsqrt_approx(float x) {
    float r; asm("rsqrt.approx.f32 %0, %1;" : "=f"(r) : "f"(x)); return r;
}
__device__ __forceinline__ float warp_sum(float v) {
#pragma unroll
    for (int o = 16; o > 0; o >>= 1) v += __shfl_down_sync(0xffffffffu, v, o);
    return v;
}

__device__ __forceinline__ void make_frame(const float n[3], const float ca[3], const float c[3],
                                           float e1[3], float e2[3], float e3[3]) {
    e1[0] = c[0] - ca[0]; e1[1] = c[1] - ca[1]; e1[2] = c[2] - ca[2];
    float s1 = e1[0]*e1[0] + e1[1]*e1[1] + e1[2]*e1[2];
    float i1 = rsqrt_approx(fmaxf(s1, 1e-6f));
    e1[0] *= i1; e1[1] *= i1; e1[2] *= i1;
    float v2[3] = { n[0]-ca[0], n[1]-ca[1], n[2]-ca[2] };
    float dt = e1[0]*v2[0] + e1[1]*v2[1] + e1[2]*v2[2];
    e2[0] = v2[0] - dt*e1[0]; e2[1] = v2[1] - dt*e1[1]; e2[2] = v2[2] - dt*e1[2];
    float s2 = e2[0]*e2[0] + e2[1]*e2[1] + e2[2]*e2[2];
    float i2 = rsqrt_approx(fmaxf(s2, 1e-6f));
    e2[0] *= i2; e2[1] *= i2; e2[2] *= i2;
    e3[0] = e1[1]*e2[2] - e1[2]*e2[1];
    e3[1] = e1[2]*e2[0] - e1[0]*e2[2];
    e3[2] = e1[0]*e2[1] - e1[1]*e2[0];
}

__device__ __forceinline__ void compute_Qo(const float* __restrict__ pred,
                                           const float* __restrict__ gt,
                                           int l, int i, float* dst /*12 floats*/) {
    const float* gb = gt + (size_t)i * NA * 3;
    float gn[3]  = { gb[0], gb[1], gb[2] };
    float gca[3] = { gb[3], gb[4], gb[5] };
    float gc[3]  = { gb[6], gb[7], gb[8] };
    float e1g[3], e2g[3], e3g[3];
    make_frame(gn, gca, gc, e1g, e2g, e3g);

    const float* pb = pred + (size_t)(l * NR + i) * NA * 3;
    float pn[3]  = { pb[0], pb[1], pb[2] };
    float pca[3] = { pb[3], pb[4], pb[5] };
    float pc[3]  = { pb[6], pb[7], pb[8] };
    float e1p[3], e2p[3], e3p[3];
    make_frame(pn, pca, pc, e1p, e2p, e3p);

#pragma unroll
    for (int d = 0; d < 3; d++) {
        float q0 = e1p[d]*e1g[0] + e2p[d]*e2g[0] + e3p[d]*e3g[0];
        float q1 = e1p[d]*e1g[1] + e2p[d]*e2g[1] + e3p[d]*e3g[1];
        float q2 = e1p[d]*e1g[2] + e2p[d]*e2g[2] + e3p[d]*e3g[2];
        dst[3*d+0] = q0; dst[3*d+1] = q1; dst[3*d+2] = q2;
        dst[9 + d] = pca[d] - (q0*gca[0] + q1*gca[1] + q2*gca[2]);
    }
}

__device__ __forceinline__ int atom_bits(const float* __restrict__ am, int i) {
    // am row: 14 floats, 56B stride -> always 8B aligned; 7x LDG.64
    const float2* r = (const float2*)(am + (size_t)i * NA);
    int bits = 0;
#pragma unroll
    for (int k = 0; k < 7; k++) {
        float2 f = r[k];
        if (f.x > 0.f) bits |= (1 << (2 * k));
        if (f.y > 0.f) bits |= (1 << (2 * k + 1));
    }
    return bits;
}

// ---- single fused kernel: 1D grid, blocks [0,NFAPE) = fape, [NFAPE,...) = lddt ----
// block = 256 threads (32 x 8); fape thread handles 4 i-rows (ty + 8r) for one j.
__global__ __launch_bounds__(256) void fused_kernel(const float* __restrict__ pred,
                                                    const float* __restrict__ gt,
                                                    const float* __restrict__ am,
                                                    const int* __restrict__ batch,
                                                    const int* __restrict__ chain,
                                                    float* __restrict__ out) {
    const int tid = threadIdx.x;
    const int tx = tid & 31, ty = tid >> 5;
    const int b = blockIdx.x;

    if (b >= NFAPE) {
        // ================= lDDT: 96 blocks x 8 rows =================
        __shared__ float sg[NR][3];
        __shared__ float sp[NR][3];
        __shared__ int   srm[NR];
        __shared__ float lred[8][2];
        for (int j = tid; j < NR; j += 256) {
            const float* gp = gt + ((size_t)j * NA + 1) * 3;
            sg[j][0] = gp[0]; sg[j][1] = gp[1]; sg[j][2] = gp[2];
            const float* pp = pred + ((size_t)(1 * NR + j) * NA + 1) * 3;  // pred[-1]
            sp[j][0] = pp[0]; sp[j][1] = pp[1]; sp[j][2] = pp[2];
            srm[j] = (atom_bits(am, j) != 0);
        }
        __syncthreads();

        const int i0 = (b - NFAPE) * ROWS_PER_LDDT;
#pragma unroll
        for (int r = 0; r < ROWS_PER_LDDT; r++) {
            const int i = i0 + r;
            const float gix = sg[i][0], giy = sg[i][1], giz = sg[i][2];
            const float pix = sp[i][0], piy = sp[i][1], piz = sp[i][2];
            float suml = 0.f, cnt = 0.f;
            if (srm[i]) {
                for (int j = tid; j < NR; j += 256) {
                    if (j == i || !srm[j]) continue;
                    float dx = gix - sg[j][0], dy = giy - sg[j][1], dz = giz - sg[j][2];
                    float gd = sqrt_approx(fmaxf(dx*dx + dy*dy + dz*dz, 1e-6f));
                    if (gd < 15.f) {
                        float ex = pix - sp[j][0], ey = piy - sp[j][1], ez = piz - sp[j][2];
                        float d = sqrt_approx(fmaxf(ex*ex + ey*ey + ez*ez, 1e-6f));
                        float derr = fabsf(gd - d);
                        int c = (derr < 0.5f) + (derr < 1.0f) + (derr < 2.0f) + (derr < 4.0f);
                        suml += 0.25f * (float)c;
                        cnt  += 1.f;
                    }
                }
            }
            float v0 = warp_sum(suml), v1 = warp_sum(cnt);
            if (tx == 0) { lred[ty][0] = v0; lred[ty][1] = v1; }
            __syncthreads();
            if (tid == 0) {
                float s = 0.f, c = 0.f;
#pragma unroll
                for (int w = 0; w < 8; w++) { s += lred[w][0]; c += lred[w][1]; }
                out[OFF_LDDT + i] = s / fmaxf(c, 1e-6f);
            }
            __syncthreads();
        }
        return;
    }

    // ================= FAPE tile =================
    const int l = b / (NTILE * NTILE);
    const int t = b % (NTILE * NTILE);
    const int i0 = (t / NTILE) * TILE, j0 = (t % NTILE) * TILE;
    float* out_ae = out + OFF_AE;

    __shared__ int sSkip;
    if (tid == 0)
        sSkip = (batch[i0] > batch[j0 + TILE - 1]) || (batch[j0] > batch[i0 + TILE - 1]);
    __syncthreads();

    if (sSkip) {
        // nres contribution still required from (l==0, j_tile==0) blocks
        if (l == 0 && j0 == 0 && tid < TILE) {
            float n = warp_sum((atom_bits(am, i0 + tid) != 0) ? 1.f : 0.f);
            if (tid == 0) atomicAdd(&g_acc[8], n);
        }
        if (l == 1) {
#pragma unroll
            for (int r = 0; r < 4; r++)
                out_ae[(size_t)(i0 + ty + 8 * r) * NR + (j0 + tx)] = 0.f;
        }
        if (tid == 0) {
            __threadfence();
            unsigned done = atomicAdd(&g_cnt, 1u);
            if (done == NFAPE - 1) {
                float nres = fmaxf(g_acc[8], 1e-6f);
                float invCS = 0.1f / fmaxf(g_acc[4], 1e-6f);
                float invCO = 0.1f / fmaxf(g_acc[5], 1e-6f);
                out[0] = g_acc[0] * invCS + g_acc[2] * invCO;
                out[1] = g_acc[1] * invCS + g_acc[3] * invCO;
                out[2] = g_acc[6] / nres;
                out[3] = g_acc[7] / nres;
#pragma unroll
                for (int k = 0; k < 9; k++) g_acc[k] = 0.f;
                __threadfence();
                g_cnt = 0u;
            }
        }
        return;
    }

    __shared__ float4 sP[TILE * 15];
    __shared__ float4 sG[TILE * 15];
    __shared__ float  sQ[TILE * 12];
    __shared__ int    sBatI[TILE], sBatJ[TILE], sBitI[TILE], sBitJ[TILE], sChI[TILE], sChJ[TILE];
    __shared__ float  sred[8][5];

    if (tid < TILE) {
        compute_Qo(pred, gt, l, i0 + tid, &sQ[tid * 12]);
        sBatI[tid] = batch[i0 + tid];
        sChI[tid]  = chain[i0 + tid];
        sBitI[tid] = atom_bits(am, i0 + tid);
    } else if (tid < 2 * TILE) {
        int u = tid - TILE;
        sBatJ[u] = batch[j0 + u];
        sChJ[u]  = chain[j0 + u];
        sBitJ[u] = atom_bits(am, j0 + u);
    }
    for (int u = tid - 64; u >= 0 && u < TILE * NA; u += 192) {
        int j = u / NA, a = u % NA;
        const float* pp = pred + ((size_t)(l * NR + j0 + j) * NA + a) * 3;
        sP[j * 15 + a] = make_float4(pp[0], pp[1], pp[2], 0.f);
        const float* gp = gt + ((size_t)(j0 + j) * NA + a) * 3;
        sG[j * 15 + a] = make_float4(gp[0], gp[1], gp[2], 0.f);
    }
    __syncthreads();

    // nres contribution (24 blocks: l==0, j_tile==0)
    if (l == 0 && j0 == 0 && tid < TILE) {
        float n = warp_sum((sBitI[tid] != 0) ? 1.f : 0.f);
        if (tid == 0) atomicAdd(&g_acc[8], n);
    }

    const int batJ = sBatJ[tx], bitJ = sBitJ[tx];
    float q[4][12];
    unsigned mb[4];
#pragma unroll
    for (int r = 0; r < 4; r++) {
        const int row = ty + 8 * r;
#pragma unroll
        for (int k = 0; k < 12; k++) q[r][k] = sQ[row * 12 + k];
        mb[r] = (sBatI[row] == batJ) ? (unsigned)(sBitI[row] & bitJ) : 0u;
    }

    float se[4] = {0.f, 0.f, 0.f, 0.f};
#pragma unroll
    for (int a = 0; a < NA; a++) {
        const float4 g = sG[tx * 15 + a];
        const float4 p = sP[tx * 15 + a];
#pragma unroll
        for (int r = 0; r < 4; r++) {
            float w0 = fmaf(q[r][0], g.x, fmaf(q[r][1], g.y, fmaf(q[r][2], g.z, q[r][9])));
            float w1 = fmaf(q[r][3], g.x, fmaf(q[r][4], g.y, fmaf(q[r][5], g.z, q[r][10])));
            float w2 = fmaf(q[r][6], g.x, fmaf(q[r][7], g.y, fmaf(q[r][8], g.z, q[r][11])));
            float d0 = p.x - w0, d1 = p.y - w1, d2 = p.z - w2;
            float n2 = fmaf(d0, d0, fmaf(d1, d1, d2 * d2));
            float err = sqrt_approx(fmaxf(n2, 1e-6f));
            se[r] += ((mb[r] >> a) & 1u) ? err : 0.f;
        }
    }

    float pIntra = 0.f, pInter = 0.f, pCntS = 0.f, pCntO = 0.f, pDiag = 0.f;
    const int chJ = sChJ[tx];
#pragma unroll
    for (int r = 0; r < 4; r++) {
        const int row = ty + 8 * r;
        const int i = i0 + row, j = j0 + tx;
        float fape = __fdividef(se[r], fmaxf((float)__popc(mb[r]), 1e-6f));
        if (l == 1) out_ae[(size_t)i * NR + j] = fape;
        if (mb[r] != 0u) {
            float clip = fminf(fape, 10.f);
            if (sChI[row] == chJ) { pIntra += clip; pCntS += 1.f; }
            else                  { pInter += clip; pCntO += 1.f; }
        }
        if (i == j) {
            pDiag += fape;
            if (l == 1) out[OFF_RE + i] = fape;
        }
    }

    float vals[5] = { pIntra, pInter, pCntS, pCntO, pDiag };
#pragma unroll
    for (int k = 0; k < 5; k++) {
        float v = warp_sum(vals[k]);
        if (tx == 0) sred[ty][k] = v;
    }
    __syncthreads();
    if (tid < 5) {
        float v = 0.f;
#pragma unroll
        for (int w = 0; w < 8; w++) v += sred[w][tid];
        if (tid == 0) atomicAdd(&g_acc[0 + l], v);
        else if (tid == 1) atomicAdd(&g_acc[2 + l], v);
        else if (tid == 2) { if (l == 0) atomicAdd(&g_acc[4], v); }
        else if (tid == 3) { if (l == 0) atomicAdd(&g_acc[5], v); }
        else atomicAdd(&g_acc[6 + l], v);
    }

    __syncthreads();
    if (tid == 0) {
        __threadfence();
        unsigned done = atomicAdd(&g_cnt, 1u);
        if (done == NFAPE - 1) {
            float nres = fmaxf(g_acc[8], 1e-6f);
            float invCS = 0.1f / fmaxf(g_acc[4], 1e-6f);
            float invCO = 0.1f / fmaxf(g_acc[5], 1e-6f);
            out[0] = g_acc[0] * invCS + g_acc[2] * invCO;  // fape_loss[0]
            out[1] = g_acc[1] * invCS + g_acc[3] * invCO;  // fape_loss[1]
            out[2] = g_acc[6] / nres;                      // rotamer_loss[0]
            out[3] = g_acc[7] / nres;                      // rotamer_loss[1]
#pragma unroll
            for (int k = 0; k < 9; k++) g_acc[k] = 0.f;    // reset for next replay
            __threadfence();
            g_cnt = 0u;
        }
    }
}

extern "C" void kernel_launch(void* const* d_in, const int* in_sizes, int n_in,
                              void* d_out, int out_size) {
    const float* pred  = (const float*)d_in[0];
    const float* gt    = (const float*)d_in[1];
    const float* am    = (const float*)d_in[2];
    const int*   batch = (const int*)d_in[3];
    const int*   chain = (const int*)d_in[4];
    float* out = (float*)d_out;

    fused_kernel<<<NFAPE + NLDDT, 256>>>(pred, gt, am, batch, chain, out);
}